// round 15
// baseline (speedup 1.0000x reference)
#include <cuda_runtime.h>
#include <cstdint>
#include <cstddef>

#define N0 4096
#define N1 3686
#define N2 2580
#define N3 1548
#define DIMS 64
#define W0 128
#define W1 116
#define W2 81
#define W3 49
#define SORTN 4096
#define FULLMASK 0xffffffffu

static __host__ __device__ constexpr size_t alignup(size_t x) { return (x + 255) & ~(size_t)255; }

static constexpr size_t A_CB0  = 0;
static constexpr size_t A_CB1  = A_CB0  + alignup((size_t)N0 * W0 * 4);
static constexpr size_t A_CB2  = A_CB1  + alignup((size_t)N1 * W1 * 4);
static constexpr size_t A_CB3  = A_CB2  + alignup((size_t)N2 * W2 * 4);
static constexpr size_t A_T    = A_CB3  + alignup((size_t)N3 * W3 * 4);
static constexpr size_t A_U    = A_T    + alignup((size_t)N0 * DIMS * 4);
static constexpr size_t A_H    = A_U    + alignup((size_t)N0 * DIMS * 4);
static constexpr size_t A_D0   = A_H    + alignup((size_t)N0 * DIMS * 4);
static constexpr size_t A_D1   = A_D0   + alignup((size_t)N0 * DIMS * 4);
static constexpr size_t A_D2   = A_D1   + alignup((size_t)N1 * DIMS * 4);
static constexpr size_t A_KEYS = A_D2   + alignup((size_t)N2 * DIMS * 4);
static constexpr size_t A_I0   = A_KEYS + alignup((size_t)SORTN * 8);
static constexpr size_t A_I1   = A_I0   + alignup((size_t)SORTN * 4);
static constexpr size_t A_I2   = A_I1   + alignup((size_t)SORTN * 4);
static constexpr size_t A_R0   = A_I2   + alignup((size_t)SORTN * 4);
static constexpr size_t A_R1   = A_R0   + alignup((size_t)SORTN * 4);
static constexpr size_t A_R2   = A_R1   + alignup((size_t)SORTN * 4);
static constexpr size_t A_RS0  = A_R2   + alignup((size_t)SORTN * 4);
static constexpr size_t A_RS1  = A_RS0  + alignup((size_t)SORTN * 4);
static constexpr size_t ARENA_BYTES = A_RS1 + alignup((size_t)SORTN * 4);

__device__ __align__(256) unsigned char g_arena[ARENA_BYTES];

// ---- XLA f32 tanh (Eigen ptanh) + logistic expansion ----
__device__ __forceinline__ float xla_tanhf(float x) {
    if (fabsf(x) < 0.0004f) return x;
    float xc = fminf(fmaxf(x, -7.90531110763549805f), 7.90531110763549805f);
    float x2 = xc * xc;
    float p = -2.76076847742355e-16f;
    p = fmaf(p, x2, 2.00018790482477e-13f);
    p = fmaf(p, x2, -8.60467152213735e-11f);
    p = fmaf(p, x2, 5.12229709037114e-08f);
    p = fmaf(p, x2, 1.48572235717979e-05f);
    p = fmaf(p, x2, 6.37261928875436e-04f);
    p = fmaf(p, x2, 4.89352455891786e-03f);
    float num = xc * p;
    float q = 1.19825839466702e-06f;
    q = fmaf(q, x2, 1.18534705686654e-04f);
    q = fmaf(q, x2, 2.26843463243900e-03f);
    q = fmaf(q, x2, 4.89352518554385e-03f);
    return num / q;
}
__device__ __forceinline__ float xla_sigmoidf(float x) {
    return fmaf(0.5f, xla_tanhf(0.5f * x), 0.5f);
}

// ---- fused: pack bits + count + t = g0 @ h (warp0 ascending, inv = 1/count) ----
__global__ void k_packspmm(const float* __restrict__ g, const float* __restrict__ h,
                           unsigned* __restrict__ bits, float* __restrict__ RS,
                           float* __restrict__ t, int n, int Wl) {
    __shared__ unsigned rb[W0];
    __shared__ int wcnt[8];
    int r = blockIdx.x;
    int tid = threadIdx.x;
    int lane = tid & 31, wp = tid >> 5;
    const float* row = g + (size_t)r * n;
    int cnt = 0;
    for (int w = wp; w < Wl; w += 8) {
        int c = (w << 5) + lane;
        float v = (c < n) ? row[c] : 0.f;
        unsigned m = __ballot_sync(FULLMASK, v != 0.f);
        if (lane == 0) { bits[(size_t)r * Wl + w] = m; rb[w] = m; cnt += __popc(m); }
    }
    if (lane == 0) wcnt[wp] = cnt;
    __syncthreads();
    if (wp == 0) {
        int s = 0;
#pragma unroll
        for (int i = 0; i < 8; ++i) s += wcnt[i];
        if (lane == 0) RS[r] = (float)s;
        float inv = 1.0f / (float)s;
        const float2* h2 = (const float2*)h;
        float a0 = 0.f, a1 = 0.f;
        for (int w = 0; w < Wl; ++w) {
            unsigned word = rb[w];
            int cb = w << 5;
            while (word) {
                int c = cb + __ffs(word) - 1;
                word &= word - 1;
                float2 v = __ldg(&h2[(size_t)c * 32 + lane]);
                a0 = fmaf(inv, v.x, a0);
                a1 = fmaf(inv, v.y, a1);
            }
        }
        ((float2*)t)[(size_t)r * 32 + lane] = make_float2(a0, a1);
    }
}

// ---- t = G @ h, bits*(1/RS); warp per row, ffs ascending; float2 ----
__global__ void k_spmm_bits(const unsigned* __restrict__ CB, const float* __restrict__ RS,
                            const float* __restrict__ h, float* __restrict__ t,
                            int n, int Wl) {
    int warp = (int)((blockIdx.x * (unsigned)blockDim.x + threadIdx.x) >> 5);
    int lane = threadIdx.x & 31;
    if (warp >= n) return;
    const unsigned* row = CB + (size_t)warp * Wl;
    const float2* h2 = (const float2*)h;
    float inv = 1.0f / RS[warp];
    float a0 = 0.f, a1 = 0.f;
    for (int wb = 0; wb < Wl; wb += 32) {
        unsigned myw = (wb + lane < Wl) ? row[wb + lane] : 0u;
        unsigned any = __ballot_sync(FULLMASK, myw != 0u);
        while (any) {
            int s = __ffs(any) - 1;
            any &= any - 1;
            unsigned word = __shfl_sync(FULLMASK, myw, s);
            int cb = (wb + s) << 5;
            while (word) {
                int c = cb + __ffs(word) - 1;
                word &= word - 1;
                float2 v = __ldg(&h2[(size_t)c * 32 + lane]);
                a0 = fmaf(inv, v.x, a0);
                a1 = fmaf(inv, v.y, a1);
            }
        }
    }
    ((float2*)t)[(size_t)warp * 32 + lane] = make_float2(a0, a1);
}

// ---- t = G @ h dense sweep (G from bits); self-popcount ----
__global__ void k_gemm_bits(const unsigned* __restrict__ CB,
                            const float* __restrict__ h, float* __restrict__ t,
                            int n, int Wl) {
    __shared__ float gs[16][65];
    __shared__ float hs[64][64];
    __shared__ float invs[16];
    int tid = threadIdx.x;
    int tx = tid & 15, ty = tid >> 4;
    int tx4 = tx * 4;
    int rbase = blockIdx.x * 16;
    {
        int lane = tid & 31, wp = tid >> 5;
        for (int rr = wp; rr < 16; rr += 8) {
            int r = rbase + rr;
            int c = 0;
            if (r < n) {
                const unsigned* rowp = CB + (size_t)r * Wl;
                for (int w = lane; w < Wl; w += 32) c += __popc(rowp[w]);
            }
#pragma unroll
            for (int off = 16; off > 0; off >>= 1) c += __shfl_xor_sync(FULLMASK, c, off);
            if (lane == 0) invs[rr] = (r < n && c > 0) ? 1.0f / (float)c : 0.f;
        }
    }
    __syncthreads();
    float acc[4] = {0.f, 0.f, 0.f, 0.f};
    const float2* h2 = (const float2*)h;

    for (int kb = 0; kb < n; kb += 64) {
        for (int i2 = tid; i2 < 1024; i2 += 256) {
            int rr = i2 >> 6, cc = i2 & 63;
            int gr = rbase + rr, gc = kb + cc;
            bool bit = (gr < n && gc < n) &&
                       ((CB[(size_t)gr * Wl + (gc >> 5)] >> (gc & 31)) & 1u);
            gs[rr][cc] = bit ? invs[rr] : 0.f;
        }
        for (int i2 = tid; i2 < 2048; i2 += 256) {
            int rr = i2 >> 5, cc = i2 & 31;
            int hr = kb + rr;
            float2 v = make_float2(0.f, 0.f);
            if (hr < n) v = __ldg(&h2[(size_t)hr * 32 + cc]);
            ((float2*)&hs[rr][0])[cc] = v;
        }
        __syncthreads();
#pragma unroll 8
        for (int kk = 0; kk < 64; ++kk) {
            float a = gs[ty][kk];
            acc[0] = fmaf(a, hs[kk][tx4 + 0], acc[0]);
            acc[1] = fmaf(a, hs[kk][tx4 + 1], acc[1]);
            acc[2] = fmaf(a, hs[kk][tx4 + 2], acc[2]);
            acc[3] = fmaf(a, hs[kk][tx4 + 3], acc[3]);
        }
        __syncthreads();
    }
    int r = rbase + ty;
    if (r < n) {
#pragma unroll
        for (int j = 0; j < 4; ++j)
            t[(size_t)r * DIMS + tx4 + j] = acc[j];
    }
}

// ---- out = relu((t @ W) + b) [+ res]; 512 thr, 8 rows/pass, 4 passes ----
__global__ void k_proj(const float* __restrict__ t, const float* __restrict__ Wm,
                       const float* __restrict__ b, const float* __restrict__ res,
                       float* __restrict__ out, int n) {
    __shared__ float Ws[64 * 64];
    __shared__ float Ts[8 * 64];
    int tid = threadIdx.x;
    int d = tid & 63;
    int r8 = tid >> 6;
    int rbase = blockIdx.x * 32;
    for (int i = tid; i < 4096; i += 512) Ws[i] = Wm[i];
    for (int pass = 0; pass < 4; ++pass) {
        int row = rbase + pass * 8 + r8;
        __syncthreads();
        Ts[tid] = (row < n) ? t[(size_t)row * DIMS + d] : 0.f;
        __syncthreads();
        if (row < n) {
            float acc = 0.f;
#pragma unroll
            for (int k = 0; k < 64; ++k)
                acc = fmaf(Ts[r8 * 64 + k], Ws[k * 64 + d], acc);
            acc = acc + b[d];
            acc = fmaxf(acc, 0.f);
            if (res) acc += res[(size_t)row * DIMS + d];
            out[(size_t)row * DIMS + d] = acc;
        }
    }
}

// ---- fused down-proj + pool scores; 512 thr ----
__global__ void k_projsc(const float* __restrict__ t, const float* __restrict__ Wm,
                         const float* __restrict__ b, const float* __restrict__ pw,
                         const float* __restrict__ pb,
                         float* __restrict__ D, unsigned long long* __restrict__ keys,
                         int n) {
    __shared__ float Ws[64 * 64];
    __shared__ float Ts[8 * 64];
    __shared__ float Os[8 * 64];
    int tid = threadIdx.x;
    int d = tid & 63;
    int r8 = tid >> 6;
    int lane = tid & 31, w = tid >> 5;
    int rbase = blockIdx.x * 32;
    for (int i = tid; i < 4096; i += 512) Ws[i] = Wm[i];
    for (int pass = 0; pass < 4; ++pass) {
        int row = rbase + pass * 8 + r8;
        __syncthreads();
        Ts[tid] = (row < n) ? t[(size_t)row * DIMS + d] : 0.f;
        __syncthreads();
        float acc = 0.f;
#pragma unroll
        for (int k = 0; k < 64; ++k)
            acc = fmaf(Ts[r8 * 64 + k], Ws[k * 64 + d], acc);
        acc = acc + b[d];
        acc = fmaxf(acc, 0.f);
        if (row < n) D[(size_t)row * DIMS + d] = acc;
        Os[tid] = acc;
        __syncthreads();
        if ((w & 1) == 0) {
            int rr = w >> 1;                       // 0..7
            int row2 = rbase + pass * 8 + rr;
            if (row2 < n) {
                float p = Os[rr * 64 + lane] * pw[lane];
                p = fmaf(Os[rr * 64 + lane + 32], pw[lane + 32], p);
#pragma unroll
                for (int off = 16; off > 0; off >>= 1) p += __shfl_xor_sync(FULLMASK, p, off);
                if (lane == 0) {
                    unsigned fb = __float_as_uint(xla_sigmoidf(p + pb[0]));
                    keys[row2] = ((unsigned long long)(~fb) << 32) | (unsigned)row2;
                }
            }
        }
    }
}

// ---- exact top-k by ranking, 2 items per warp + fused gated gather ----
__global__ void k_rank(const unsigned long long* __restrict__ keys, int n, int k,
                       const float* __restrict__ D, float* __restrict__ Hb,
                       int* __restrict__ idx_out, int* __restrict__ RANK) {
    int wid = (int)((blockIdx.x * (unsigned)blockDim.x + threadIdx.x) >> 5);
    int lane = threadIdx.x & 31;
    int i0 = wid * 2, i1 = i0 + 1;
    if (i0 >= n) return;
    unsigned long long k0 = keys[i0];
    unsigned long long k1 = (i1 < n) ? keys[i1] : 0xFFFFFFFFFFFFFFFFull;
    int c0 = 0, c1 = 0;
    int j = lane;
    for (; j + 32 < n; j += 64) {
        unsigned long long a = keys[j], bk = keys[j + 32];
        c0 += (a < k0) ? 1 : 0; c0 += (bk < k0) ? 1 : 0;
        c1 += (a < k1) ? 1 : 0; c1 += (bk < k1) ? 1 : 0;
    }
    for (; j < n; j += 32) {
        unsigned long long a = keys[j];
        c0 += (a < k0) ? 1 : 0;
        c1 += (a < k1) ? 1 : 0;
    }
#pragma unroll
    for (int off = 16; off > 0; off >>= 1) {
        c0 += __shfl_xor_sync(FULLMASK, c0, off);
        c1 += __shfl_xor_sync(FULLMASK, c1, off);
    }
    if (lane == 0) RANK[i0] = c0;
    if (c0 < k) {
        if (lane == 0) idx_out[c0] = i0;
        float s = __uint_as_float(~(unsigned)(k0 >> 32));
        float2 v = ((const float2*)D)[(size_t)i0 * 32 + lane];
        ((float2*)Hb)[(size_t)c0 * 32 + lane] = make_float2(v.x * s, v.y * s);
    }
    if (i1 < n) {
        if (lane == 0) RANK[i1] = c1;
        if (c1 < k) {
            if (lane == 0) idx_out[c1] = i1;
            float s = __uint_as_float(~(unsigned)(k1 >> 32));
            float2 v = ((const float2*)D)[(size_t)i1 * 32 + lane];
            ((float2*)Hb)[(size_t)c1 * 32 + lane] = make_float2(v.x * s, v.y * s);
        }
    }
}

// ---- streaming unpool: u[r] = RANK[r] < k ? src[RANK[r]] : 0 ; float2 ----
__global__ void k_unpool(const float* __restrict__ src, const int* __restrict__ RANK,
                         int kvalid, float* __restrict__ u, int n) {
    int i = blockIdx.x * 256 + threadIdx.x;
    if (i >= n * 32) return;
    int r = i >> 5, d = i & 31;
    int rk = RANK[r];
    float2 v = make_float2(0.f, 0.f);
    if (rk < kvalid) v = ((const float2*)src)[(size_t)rk * 32 + d];
    ((float2*)u)[(size_t)r * 32 + d] = v;
}

// ---- level-0 2-hop via row-OR over sparse neighbors; packed gathered output ----
__global__ void k_rowor(const unsigned* __restrict__ BITS0, const int* __restrict__ idx,
                        unsigned* __restrict__ CB1o, float* __restrict__ RS1o) {
    __shared__ unsigned own[W0];
    __shared__ unsigned accs[W0];
    __shared__ int cnt_sh;
    int i = blockIdx.x;
    int t = threadIdx.x;
    own[t] = BITS0[(size_t)idx[i] * W0 + t];
    if (t == 0) cnt_sh = 0;
    __syncthreads();
    unsigned a = 0;
    for (int w2 = 0; w2 < W0; ++w2) {
        unsigned word = own[w2];
        while (word) {
            int c = (w2 << 5) + __ffs(word) - 1;
            word &= word - 1;
            a |= BITS0[(size_t)c * W0 + t];
        }
    }
    accs[t] = a;
    __syncthreads();
    int lane = t & 31, wp = t >> 5;
    int cnt = 0;
    for (int ow = wp; ow < W1; ow += 4) {
        int j = (ow << 5) + lane;
        unsigned bit = 0;
        if (j < N1) {
            int col = idx[j];
            bit = (accs[col >> 5] >> (col & 31)) & 1u;
        }
        unsigned m = __ballot_sync(FULLMASK, bit);
        if (lane == 0) {
            CB1o[(size_t)i * W1 + ow] = m;
            cnt += __popc(m);
        }
    }
    if (lane == 0 && cnt) atomicAdd(&cnt_sh, cnt);
    __syncthreads();
    if (t == 0) RS1o[i] = (float)cnt_sh;
}

// ---- pairwise 2-hop, SYMMETRIC: only bx>=by blocks; emit tile + mirror ----
__global__ void k_pairb(const unsigned* __restrict__ A, const int* __restrict__ idx,
                        int kk, int Wl, int Wout, unsigned* __restrict__ CB) {
    if (blockIdx.x < blockIdx.y) return;
    __shared__ unsigned As[64 * 9];
    __shared__ unsigned Bs[64 * 9];
    __shared__ unsigned obits[128];
    __shared__ unsigned obits_t[128];
    __shared__ int ridx[64], cidx[64];
    int tid = threadIdx.x;
    int tx = tid & 15, ty = tid >> 4;
    int rbase = blockIdx.y * 64, cbase = blockIdx.x * 64;
    bool diag = (blockIdx.x == blockIdx.y);
    int ty4 = ty * 4, tx4 = tx * 4;
    if (tid < 128) { obits[tid] = 0u; obits_t[tid] = 0u; }
    if (tid < 64) {
        int r = rbase + tid;
        ridx[tid] = (r < kk) ? idx[r] : 0;
        int c = cbase + tid;
        cidx[tid] = (c < kk) ? idx[c] : 0;
    }

    unsigned acc[4][4];
#pragma unroll
    for (int i = 0; i < 4; ++i)
#pragma unroll
        for (int j = 0; j < 4; ++j) {
            bool valid = (rbase + ty4 + i < kk) && (cbase + tx4 + j < kk);
            acc[i][j] = valid ? 0u : 1u;
        }
    __syncthreads();

    bool done = false;
    for (int ch = 0; ch < Wl; ch += 8) {
        for (int i2 = tid; i2 < 512; i2 += 256) {
            int rr = i2 >> 3, ww = i2 & 7;
            int gw = ch + ww;
            bool okw = (gw < Wl);
            As[rr * 9 + ww] = (okw && rbase + rr < kk) ? A[(size_t)ridx[rr] * Wl + gw] : 0u;
            Bs[rr * 9 + ww] = (okw && cbase + rr < kk) ? A[(size_t)cidx[rr] * Wl + gw] : 0u;
        }
        __syncthreads();
        if (!done) {
#pragma unroll
            for (int w = 0; w < 8; ++w) {
                unsigned a0 = As[(ty4 + 0) * 9 + w];
                unsigned a1 = As[(ty4 + 1) * 9 + w];
                unsigned a2 = As[(ty4 + 2) * 9 + w];
                unsigned a3 = As[(ty4 + 3) * 9 + w];
                unsigned b0 = Bs[(tx4 + 0) * 9 + w];
                unsigned b1 = Bs[(tx4 + 1) * 9 + w];
                unsigned b2 = Bs[(tx4 + 2) * 9 + w];
                unsigned b3 = Bs[(tx4 + 3) * 9 + w];
                acc[0][0] |= a0 & b0; acc[0][1] |= a0 & b1; acc[0][2] |= a0 & b2; acc[0][3] |= a0 & b3;
                acc[1][0] |= a1 & b0; acc[1][1] |= a1 & b1; acc[1][2] |= a1 & b2; acc[1][3] |= a1 & b3;
                acc[2][0] |= a2 & b0; acc[2][1] |= a2 & b1; acc[2][2] |= a2 & b2; acc[2][3] |= a2 & b3;
                acc[3][0] |= a3 & b0; acc[3][1] |= a3 & b1; acc[3][2] |= a3 & b2; acc[3][3] |= a3 & b3;
            }
            bool d = true;
#pragma unroll
            for (int i = 0; i < 4; ++i)
#pragma unroll
                for (int j = 0; j < 4; ++j) d = d && (acc[i][j] != 0u);
            done = d;
        }
        if (__syncthreads_and(done ? 1 : 0)) break;
    }

    int word_half = tx >> 3;
    int shift = tx4 & 31;
#pragma unroll
    for (int i = 0; i < 4; ++i) {
        int r = rbase + ty4 + i;
        if (r < kk) {
            unsigned nib = 0;
#pragma unroll
            for (int j = 0; j < 4; ++j) {
                int c = cbase + tx4 + j;
                if (c < kk && acc[i][j]) nib |= (1u << j);
            }
            if (nib) atomicOr(&obits[(ty4 + i) * 2 + word_half], nib << shift);
        }
    }
    if (!diag) {
        int wt = ty4 >> 5;
        int sht = ty4 & 31;
#pragma unroll
        for (int j = 0; j < 4; ++j) {
            int c = cbase + tx4 + j;
            if (c < kk) {
                unsigned nib = 0;
#pragma unroll
                for (int i = 0; i < 4; ++i) {
                    int r = rbase + ty4 + i;
                    if (r < kk && acc[i][j]) nib |= (1u << i);
                }
                if (nib) atomicOr(&obits_t[(tx4 + j) * 2 + wt], nib << sht);
            }
        }
    }
    __syncthreads();
    if (tid < 128) {
        int rr = tid >> 1;
        int r = rbase + rr;
        int w = blockIdx.x * 2 + (tid & 1);
        if (r < kk && w < Wout) CB[(size_t)r * Wout + w] = obits[tid];
        if (!diag) {
            int r2 = cbase + rr;
            int w2 = blockIdx.y * 2 + (tid & 1);
            if (r2 < kk && w2 < Wout) CB[(size_t)r2 * Wout + w2] = obits_t[tid];
        }
    }
}

// ---- final proj: out2 = relu(tW+b)+res ; out3 = out2 + h_in ; 512 thr ----
__global__ void k_proj_final(const float* __restrict__ t, const float* __restrict__ Wm,
                             const float* __restrict__ b, const float* __restrict__ res,
                             const float* __restrict__ hin,
                             float* __restrict__ out2, float* __restrict__ out3, int n) {
    __shared__ float Ws[64 * 64];
    __shared__ float Ts[8 * 64];
    int tid = threadIdx.x;
    int d = tid & 63;
    int r8 = tid >> 6;
    int rbase = blockIdx.x * 32;
    for (int i = tid; i < 4096; i += 512) Ws[i] = Wm[i];
    for (int pass = 0; pass < 4; ++pass) {
        int row = rbase + pass * 8 + r8;
        __syncthreads();
        Ts[tid] = (row < n) ? t[(size_t)row * DIMS + d] : 0.f;
        __syncthreads();
        if (row < n) {
            float acc = 0.f;
#pragma unroll
            for (int k = 0; k < 64; ++k)
                acc = fmaf(Ts[r8 * 64 + k], Ws[k * 64 + d], acc);
            acc = acc + b[d];
            acc = fmaxf(acc, 0.f);
            acc += res[(size_t)row * DIMS + d];
            out2[(size_t)row * DIMS + d] = acc;
            out3[(size_t)row * DIMS + d] = acc + hin[(size_t)row * DIMS + d];
        }
    }
}

extern "C" void kernel_launch(void* const* d_in, const int* in_sizes, int n_in,
                              void* d_out, int out_size) {
    (void)in_sizes; (void)n_in; (void)out_size;
    const float* g0   = (const float*)d_in[0];
    const float* h_in = (const float*)d_in[1];
    const float* dW   = (const float*)d_in[2];
    const float* db   = (const float*)d_in[3];
    const float* uW   = (const float*)d_in[4];
    const float* ub   = (const float*)d_in[5];
    const float* pW   = (const float*)d_in[6];
    const float* pb   = (const float*)d_in[7];
    const float* bW   = (const float*)d_in[8];
    const float* bb   = (const float*)d_in[9];
    float* out = (float*)d_out;
    float* out0 = out;                               // [N2,64]
    float* out1 = out + (size_t)N2 * DIMS;           // [N1,64]
    float* out2 = out1 + (size_t)N1 * DIMS;          // [N0,64]
    float* out3 = out2 + (size_t)N0 * DIMS;          // [N0,64]

    void* basep = nullptr;
    cudaGetSymbolAddress(&basep, g_arena);
    char* base = (char*)basep;
    unsigned* CB0  = (unsigned*)(base + A_CB0);
    unsigned* CB1  = (unsigned*)(base + A_CB1);
    unsigned* CB2  = (unsigned*)(base + A_CB2);
    unsigned* CB3  = (unsigned*)(base + A_CB3);
    float*    T    = (float*)(base + A_T);
    float*    U    = (float*)(base + A_U);
    float*    Hb   = (float*)(base + A_H);
    float*    D0b  = (float*)(base + A_D0);
    float*    D1b  = (float*)(base + A_D1);
    float*    D2b  = (float*)(base + A_D2);
    unsigned long long* KEYS = (unsigned long long*)(base + A_KEYS);
    int*      I0   = (int*)(base + A_I0);
    int*      I1   = (int*)(base + A_I1);
    int*      I2   = (int*)(base + A_I2);
    int*      R0   = (int*)(base + A_R0);
    int*      R1   = (int*)(base + A_R1);
    int*      R2   = (int*)(base + A_R2);
    float*    RS0  = (float*)(base + A_RS0);
    float*    RS1  = (float*)(base + A_RS1);

    // ---------------- down level 0 ----------------
    k_packspmm<<<N0, 256>>>(g0, h_in, CB0, RS0, T, N0, W0);
    k_projsc<<<(N0 + 31) / 32, 512>>>(T, dW, db, pW, pb, D0b, KEYS, N0);
    k_rank<<<((N0 + 1) / 2 + 7) / 8, 256>>>(KEYS, N0, N1, D0b, Hb, I0, R0);
    k_rowor<<<N1, 128>>>(CB0, I0, CB1, RS1);

    // ---------------- down level 1 ----------------
    k_spmm_bits<<<(N1 + 7) / 8, 256>>>(CB1, RS1, Hb, T, N1, W1);
    k_projsc<<<(N1 + 31) / 32, 512>>>(T, dW + 4096, db + 64, pW + 64, pb + 1, D1b, KEYS, N1);
    k_rank<<<((N1 + 1) / 2 + 7) / 8, 256>>>(KEYS, N1, N2, D1b, Hb, I1, R1);
    {
        dim3 grid((N2 + 63) / 64, (N2 + 63) / 64);
        k_pairb<<<grid, 256>>>(CB1, I1, N2, W1, W2, CB2);
    }

    // ---------------- down level 2 ----------------
    k_gemm_bits<<<(N2 + 15) / 16, 256>>>(CB2, Hb, T, N2, W2);
    k_projsc<<<(N2 + 31) / 32, 512>>>(T, dW + 8192, db + 128, pW + 128, pb + 2, D2b, KEYS, N2);
    k_rank<<<((N2 + 1) / 2 + 7) / 8, 256>>>(KEYS, N2, N3, D2b, Hb, I2, R2);
    {
        dim3 grid((N3 + 63) / 64, (N3 + 63) / 64);
        k_pairb<<<grid, 256>>>(CB2, I2, N3, W2, W3, CB3);
    }

    // ---------------- bottom ----------------
    k_gemm_bits<<<(N3 + 15) / 16, 256>>>(CB3, Hb, T, N3, W3);
    k_proj<<<(N3 + 31) / 32, 512>>>(T, bW, bb, nullptr, Hb, N3);

    // ---------------- up level 0: streaming unpool, gcn over CB2 ----------------
    k_unpool<<<(N2 * 32 + 255) / 256, 256>>>(Hb, R2, N3, U, N2);
    k_gemm_bits<<<(N2 + 15) / 16, 256>>>(CB2, U, T, N2, W2);
    k_proj<<<(N2 + 31) / 32, 512>>>(T, uW, ub, D2b, out0, N2);

    // ---------------- up level 1: streaming unpool, gcn over CB1 ----------------
    k_unpool<<<(N1 * 32 + 255) / 256, 256>>>(out0, R1, N2, U, N1);
    k_spmm_bits<<<(N1 + 7) / 8, 256>>>(CB1, RS1, U, T, N1, W1);
    k_proj<<<(N1 + 31) / 32, 512>>>(T, uW + 4096, ub + 64, D1b, out1, N1);

    // ---------------- up level 2: streaming unpool, gcn over CB0 ----------------
    k_unpool<<<(N0 * 32 + 255) / 256, 256>>>(out1, R0, N1, U, N0);
    k_spmm_bits<<<(N0 + 7) / 8, 256>>>(CB0, RS0, U, T, N0, W0);
    k_proj_final<<<(N0 + 31) / 32, 512>>>(T, uW + 8192, ub + 128, D0b, h_in, out2, out3, N0);
}

// round 16
// speedup vs baseline: 1.0235x; 1.0235x over previous
#include <cuda_runtime.h>
#include <cstdint>
#include <cstddef>

#define N0 4096
#define N1 3686
#define N2 2580
#define N3 1548
#define DIMS 64
#define W0 128
#define W1 116
#define W2 81
#define W3 49
#define SORTN 4096
#define FULLMASK 0xffffffffu

static __host__ __device__ constexpr size_t alignup(size_t x) { return (x + 255) & ~(size_t)255; }

static constexpr size_t A_CB0  = 0;
static constexpr size_t A_CB1  = A_CB0  + alignup((size_t)N0 * W0 * 4);
static constexpr size_t A_CB2  = A_CB1  + alignup((size_t)N1 * W1 * 4);
static constexpr size_t A_CB3  = A_CB2  + alignup((size_t)N2 * W2 * 4);
static constexpr size_t A_T    = A_CB3  + alignup((size_t)N3 * W3 * 4);
static constexpr size_t A_U    = A_T    + alignup((size_t)N0 * DIMS * 4);
static constexpr size_t A_H    = A_U    + alignup((size_t)N0 * DIMS * 4);
static constexpr size_t A_D0   = A_H    + alignup((size_t)N0 * DIMS * 4);
static constexpr size_t A_D1   = A_D0   + alignup((size_t)N0 * DIMS * 4);
static constexpr size_t A_D2   = A_D1   + alignup((size_t)N1 * DIMS * 4);
static constexpr size_t A_KEYS = A_D2   + alignup((size_t)N2 * DIMS * 4);
static constexpr size_t A_I0   = A_KEYS + alignup((size_t)SORTN * 8);
static constexpr size_t A_I1   = A_I0   + alignup((size_t)SORTN * 4);
static constexpr size_t A_I2   = A_I1   + alignup((size_t)SORTN * 4);
static constexpr size_t A_R0   = A_I2   + alignup((size_t)SORTN * 4);
static constexpr size_t A_R1   = A_R0   + alignup((size_t)SORTN * 4);
static constexpr size_t A_R2   = A_R1   + alignup((size_t)SORTN * 4);
static constexpr size_t A_RS0  = A_R2   + alignup((size_t)SORTN * 4);
static constexpr size_t A_RS1  = A_RS0  + alignup((size_t)SORTN * 4);
static constexpr size_t ARENA_BYTES = A_RS1 + alignup((size_t)SORTN * 4);

__device__ __align__(256) unsigned char g_arena[ARENA_BYTES];

// ---- XLA f32 tanh (Eigen ptanh) + logistic expansion ----
__device__ __forceinline__ float xla_tanhf(float x) {
    if (fabsf(x) < 0.0004f) return x;
    float xc = fminf(fmaxf(x, -7.90531110763549805f), 7.90531110763549805f);
    float x2 = xc * xc;
    float p = -2.76076847742355e-16f;
    p = fmaf(p, x2, 2.00018790482477e-13f);
    p = fmaf(p, x2, -8.60467152213735e-11f);
    p = fmaf(p, x2, 5.12229709037114e-08f);
    p = fmaf(p, x2, 1.48572235717979e-05f);
    p = fmaf(p, x2, 6.37261928875436e-04f);
    p = fmaf(p, x2, 4.89352455891786e-03f);
    float num = xc * p;
    float q = 1.19825839466702e-06f;
    q = fmaf(q, x2, 1.18534705686654e-04f);
    q = fmaf(q, x2, 2.26843463243900e-03f);
    q = fmaf(q, x2, 4.89352518554385e-03f);
    return num / q;
}
__device__ __forceinline__ float xla_sigmoidf(float x) {
    return fmaf(0.5f, xla_tanhf(0.5f * x), 0.5f);
}

// ---- fused: pack bits + count + t = g0 @ h (warp0 ascending, inv = 1/count) ----
__global__ void k_packspmm(const float* __restrict__ g, const float* __restrict__ h,
                           unsigned* __restrict__ bits, float* __restrict__ RS,
                           float* __restrict__ t, int n, int Wl) {
    __shared__ unsigned rb[W0];
    __shared__ int wcnt[8];
    int r = blockIdx.x;
    int tid = threadIdx.x;
    int lane = tid & 31, wp = tid >> 5;
    const float* row = g + (size_t)r * n;
    int cnt = 0;
    for (int w = wp; w < Wl; w += 8) {
        int c = (w << 5) + lane;
        float v = (c < n) ? row[c] : 0.f;
        unsigned m = __ballot_sync(FULLMASK, v != 0.f);
        if (lane == 0) { bits[(size_t)r * Wl + w] = m; rb[w] = m; cnt += __popc(m); }
    }
    if (lane == 0) wcnt[wp] = cnt;
    __syncthreads();
    if (wp == 0) {
        int s = 0;
#pragma unroll
        for (int i = 0; i < 8; ++i) s += wcnt[i];
        if (lane == 0) RS[r] = (float)s;
        float inv = 1.0f / (float)s;
        const float2* h2 = (const float2*)h;
        float a0 = 0.f, a1 = 0.f;
        for (int w = 0; w < Wl; ++w) {
            unsigned word = rb[w];
            int cb = w << 5;
            while (word) {
                int c = cb + __ffs(word) - 1;
                word &= word - 1;
                float2 v = __ldg(&h2[(size_t)c * 32 + lane]);
                a0 = fmaf(inv, v.x, a0);
                a1 = fmaf(inv, v.y, a1);
            }
        }
        ((float2*)t)[(size_t)r * 32 + lane] = make_float2(a0, a1);
    }
}

// ---- t = G @ h, bits*(1/RS); warp per row, ffs ascending; float2 ----
__global__ void k_spmm_bits(const unsigned* __restrict__ CB, const float* __restrict__ RS,
                            const float* __restrict__ h, float* __restrict__ t,
                            int n, int Wl) {
    int warp = (int)((blockIdx.x * (unsigned)blockDim.x + threadIdx.x) >> 5);
    int lane = threadIdx.x & 31;
    if (warp >= n) return;
    const unsigned* row = CB + (size_t)warp * Wl;
    const float2* h2 = (const float2*)h;
    float inv = 1.0f / RS[warp];
    float a0 = 0.f, a1 = 0.f;
    for (int wb = 0; wb < Wl; wb += 32) {
        unsigned myw = (wb + lane < Wl) ? row[wb + lane] : 0u;
        unsigned any = __ballot_sync(FULLMASK, myw != 0u);
        while (any) {
            int s = __ffs(any) - 1;
            any &= any - 1;
            unsigned word = __shfl_sync(FULLMASK, myw, s);
            int cb = (wb + s) << 5;
            while (word) {
                int c = cb + __ffs(word) - 1;
                word &= word - 1;
                float2 v = __ldg(&h2[(size_t)c * 32 + lane]);
                a0 = fmaf(inv, v.x, a0);
                a1 = fmaf(inv, v.y, a1);
            }
        }
    }
    ((float2*)t)[(size_t)warp * 32 + lane] = make_float2(a0, a1);
}

// ---- t = G @ h dense sweep (G from bits); self-popcount ----
__global__ void k_gemm_bits(const unsigned* __restrict__ CB,
                            const float* __restrict__ h, float* __restrict__ t,
                            int n, int Wl) {
    __shared__ float gs[16][65];
    __shared__ float hs[64][64];
    __shared__ float invs[16];
    int tid = threadIdx.x;
    int tx = tid & 15, ty = tid >> 4;
    int tx4 = tx * 4;
    int rbase = blockIdx.x * 16;
    {
        int lane = tid & 31, wp = tid >> 5;
        for (int rr = wp; rr < 16; rr += 8) {
            int r = rbase + rr;
            int c = 0;
            if (r < n) {
                const unsigned* rowp = CB + (size_t)r * Wl;
                for (int w = lane; w < Wl; w += 32) c += __popc(rowp[w]);
            }
#pragma unroll
            for (int off = 16; off > 0; off >>= 1) c += __shfl_xor_sync(FULLMASK, c, off);
            if (lane == 0) invs[rr] = (r < n && c > 0) ? 1.0f / (float)c : 0.f;
        }
    }
    __syncthreads();
    float acc[4] = {0.f, 0.f, 0.f, 0.f};
    const float2* h2 = (const float2*)h;

    for (int kb = 0; kb < n; kb += 64) {
        for (int i2 = tid; i2 < 1024; i2 += 256) {
            int rr = i2 >> 6, cc = i2 & 63;
            int gr = rbase + rr, gc = kb + cc;
            bool bit = (gr < n && gc < n) &&
                       ((CB[(size_t)gr * Wl + (gc >> 5)] >> (gc & 31)) & 1u);
            gs[rr][cc] = bit ? invs[rr] : 0.f;
        }
        for (int i2 = tid; i2 < 2048; i2 += 256) {
            int rr = i2 >> 5, cc = i2 & 31;
            int hr = kb + rr;
            float2 v = make_float2(0.f, 0.f);
            if (hr < n) v = __ldg(&h2[(size_t)hr * 32 + cc]);
            ((float2*)&hs[rr][0])[cc] = v;
        }
        __syncthreads();
#pragma unroll 8
        for (int kk = 0; kk < 64; ++kk) {
            float a = gs[ty][kk];
            acc[0] = fmaf(a, hs[kk][tx4 + 0], acc[0]);
            acc[1] = fmaf(a, hs[kk][tx4 + 1], acc[1]);
            acc[2] = fmaf(a, hs[kk][tx4 + 2], acc[2]);
            acc[3] = fmaf(a, hs[kk][tx4 + 3], acc[3]);
        }
        __syncthreads();
    }
    int r = rbase + ty;
    if (r < n) {
#pragma unroll
        for (int j = 0; j < 4; ++j)
            t[(size_t)r * DIMS + tx4 + j] = acc[j];
    }
}

// ---- out = relu((t @ W) + b) [+ res]; 512 thr ----
__global__ void k_proj(const float* __restrict__ t, const float* __restrict__ Wm,
                       const float* __restrict__ b, const float* __restrict__ res,
                       float* __restrict__ out, int n) {
    __shared__ float Ws[64 * 64];
    __shared__ float Ts[8 * 64];
    int tid = threadIdx.x;
    int d = tid & 63;
    int r8 = tid >> 6;
    int rbase = blockIdx.x * 32;
    for (int i = tid; i < 4096; i += 512) Ws[i] = Wm[i];
    for (int pass = 0; pass < 4; ++pass) {
        int row = rbase + pass * 8 + r8;
        __syncthreads();
        Ts[tid] = (row < n) ? t[(size_t)row * DIMS + d] : 0.f;
        __syncthreads();
        if (row < n) {
            float acc = 0.f;
#pragma unroll
            for (int k = 0; k < 64; ++k)
                acc = fmaf(Ts[r8 * 64 + k], Ws[k * 64 + d], acc);
            acc = acc + b[d];
            acc = fmaxf(acc, 0.f);
            if (res) acc += res[(size_t)row * DIMS + d];
            out[(size_t)row * DIMS + d] = acc;
        }
    }
}

// ---- fused down-proj + pool scores; 512 thr ----
__global__ void k_projsc(const float* __restrict__ t, const float* __restrict__ Wm,
                         const float* __restrict__ b, const float* __restrict__ pw,
                         const float* __restrict__ pb,
                         float* __restrict__ D, unsigned long long* __restrict__ keys,
                         int n) {
    __shared__ float Ws[64 * 64];
    __shared__ float Ts[8 * 64];
    __shared__ float Os[8 * 64];
    int tid = threadIdx.x;
    int d = tid & 63;
    int r8 = tid >> 6;
    int lane = tid & 31, w = tid >> 5;
    int rbase = blockIdx.x * 32;
    for (int i = tid; i < 4096; i += 512) Ws[i] = Wm[i];
    for (int pass = 0; pass < 4; ++pass) {
        int row = rbase + pass * 8 + r8;
        __syncthreads();
        Ts[tid] = (row < n) ? t[(size_t)row * DIMS + d] : 0.f;
        __syncthreads();
        float acc = 0.f;
#pragma unroll
        for (int k = 0; k < 64; ++k)
            acc = fmaf(Ts[r8 * 64 + k], Ws[k * 64 + d], acc);
        acc = acc + b[d];
        acc = fmaxf(acc, 0.f);
        if (row < n) D[(size_t)row * DIMS + d] = acc;
        Os[tid] = acc;
        __syncthreads();
        if ((w & 1) == 0) {
            int rr = w >> 1;
            int row2 = rbase + pass * 8 + rr;
            if (row2 < n) {
                float p = Os[rr * 64 + lane] * pw[lane];
                p = fmaf(Os[rr * 64 + lane + 32], pw[lane + 32], p);
#pragma unroll
                for (int off = 16; off > 0; off >>= 1) p += __shfl_xor_sync(FULLMASK, p, off);
                if (lane == 0) {
                    unsigned fb = __float_as_uint(xla_sigmoidf(p + pb[0]));
                    keys[row2] = ((unsigned long long)(~fb) << 32) | (unsigned)row2;
                }
            }
        }
    }
}

// ---- exact top-k by ranking, 2 items per warp + fused gated gather ----
__global__ void k_rank(const unsigned long long* __restrict__ keys, int n, int k,
                       const float* __restrict__ D, float* __restrict__ Hb,
                       int* __restrict__ idx_out, int* __restrict__ RANK) {
    int wid = (int)((blockIdx.x * (unsigned)blockDim.x + threadIdx.x) >> 5);
    int lane = threadIdx.x & 31;
    int i0 = wid * 2, i1 = i0 + 1;
    if (i0 >= n) return;
    unsigned long long k0 = keys[i0];
    unsigned long long k1 = (i1 < n) ? keys[i1] : 0xFFFFFFFFFFFFFFFFull;
    int c0 = 0, c1 = 0;
    int j = lane;
    for (; j + 32 < n; j += 64) {
        unsigned long long a = keys[j], bk = keys[j + 32];
        c0 += (a < k0) ? 1 : 0; c0 += (bk < k0) ? 1 : 0;
        c1 += (a < k1) ? 1 : 0; c1 += (bk < k1) ? 1 : 0;
    }
    for (; j < n; j += 32) {
        unsigned long long a = keys[j];
        c0 += (a < k0) ? 1 : 0;
        c1 += (a < k1) ? 1 : 0;
    }
#pragma unroll
    for (int off = 16; off > 0; off >>= 1) {
        c0 += __shfl_xor_sync(FULLMASK, c0, off);
        c1 += __shfl_xor_sync(FULLMASK, c1, off);
    }
    if (lane == 0) RANK[i0] = c0;
    if (c0 < k) {
        if (lane == 0) idx_out[c0] = i0;
        float s = __uint_as_float(~(unsigned)(k0 >> 32));
        float2 v = ((const float2*)D)[(size_t)i0 * 32 + lane];
        ((float2*)Hb)[(size_t)c0 * 32 + lane] = make_float2(v.x * s, v.y * s);
    }
    if (i1 < n) {
        if (lane == 0) RANK[i1] = c1;
        if (c1 < k) {
            if (lane == 0) idx_out[c1] = i1;
            float s = __uint_as_float(~(unsigned)(k1 >> 32));
            float2 v = ((const float2*)D)[(size_t)i1 * 32 + lane];
            ((float2*)Hb)[(size_t)c1 * 32 + lane] = make_float2(v.x * s, v.y * s);
        }
    }
}

// ---- streaming unpool: u[r] = RANK[r] < k ? src[RANK[r]] : 0 ; float2 ----
__global__ void k_unpool(const float* __restrict__ src, const int* __restrict__ RANK,
                         int kvalid, float* __restrict__ u, int n) {
    int i = blockIdx.x * 256 + threadIdx.x;
    if (i >= n * 32) return;
    int r = i >> 5, d = i & 31;
    int rk = RANK[r];
    float2 v = make_float2(0.f, 0.f);
    if (rk < kvalid) v = ((const float2*)src)[(size_t)rk * 32 + d];
    ((float2*)u)[(size_t)r * 32 + d] = v;
}

// ---- level-0 2-hop via row-OR: neighbor-list extraction + smem idx staging ----
__global__ void k_rowor(const unsigned* __restrict__ BITS0, const int* __restrict__ idx,
                        unsigned* __restrict__ CB1o, float* __restrict__ RS1o) {
    __shared__ unsigned accs[W0];
    __shared__ int nb[512];
    __shared__ int nbcnt;
    __shared__ int idxs[N1];
    __shared__ int cnt_sh;
    int i = blockIdx.x;
    int t = threadIdx.x;            // 128 threads
    if (t == 0) { nbcnt = 0; cnt_sh = 0; }
    __syncthreads();
    // stage idx into smem (coalesced) + extract this row's neighbor list
    {
        unsigned w = BITS0[(size_t)idx[i] * W0 + t];
        if (w) {
            int c = __popc(w);
            int basei = atomicAdd(&nbcnt, c);
            int cb = t << 5;
            while (w) {
                nb[basei++] = cb + __ffs(w) - 1;
                w &= w - 1;
            }
        }
    }
    for (int j = t; j < N1; j += 128) idxs[j] = idx[j];
    __syncthreads();
    // OR the neighbor rows (coalesced across t per neighbor)
    unsigned a = 0;
    int cnt = nbcnt;
    for (int q = 0; q < cnt; ++q)
        a |= BITS0[(size_t)nb[q] * W0 + t];
    accs[t] = a;
    __syncthreads();
    // gather bits at idx columns, pack, count
    int lane = t & 31, wp = t >> 5;
    int lc = 0;
    for (int ow = wp; ow < W1; ow += 4) {
        int j = (ow << 5) + lane;
        unsigned bit = 0;
        if (j < N1) {
            int col = idxs[j];
            bit = (accs[col >> 5] >> (col & 31)) & 1u;
        }
        unsigned m = __ballot_sync(FULLMASK, bit);
        if (lane == 0) {
            CB1o[(size_t)i * W1 + ow] = m;
            lc += __popc(m);
        }
    }
    if (lane == 0 && lc) atomicAdd(&cnt_sh, lc);
    __syncthreads();
    if (t == 0) RS1o[i] = (float)cnt_sh;
}

// ---- pairwise 2-hop, SYMMETRIC: only bx>=by blocks; emit tile + mirror ----
__global__ void k_pairb(const unsigned* __restrict__ A, const int* __restrict__ idx,
                        int kk, int Wl, int Wout, unsigned* __restrict__ CB) {
    if (blockIdx.x < blockIdx.y) return;
    __shared__ unsigned As[64 * 9];
    __shared__ unsigned Bs[64 * 9];
    __shared__ unsigned obits[128];
    __shared__ unsigned obits_t[128];
    __shared__ int ridx[64], cidx[64];
    int tid = threadIdx.x;
    int tx = tid & 15, ty = tid >> 4;
    int rbase = blockIdx.y * 64, cbase = blockIdx.x * 64;
    bool diag = (blockIdx.x == blockIdx.y);
    int ty4 = ty * 4, tx4 = tx * 4;
    if (tid < 128) { obits[tid] = 0u; obits_t[tid] = 0u; }
    if (tid < 64) {
        int r = rbase + tid;
        ridx[tid] = (r < kk) ? idx[r] : 0;
        int c = cbase + tid;
        cidx[tid] = (c < kk) ? idx[c] : 0;
    }

    unsigned acc[4][4];
#pragma unroll
    for (int i = 0; i < 4; ++i)
#pragma unroll
        for (int j = 0; j < 4; ++j) {
            bool valid = (rbase + ty4 + i < kk) && (cbase + tx4 + j < kk);
            acc[i][j] = valid ? 0u : 1u;
        }
    __syncthreads();

    bool done = false;
    for (int ch = 0; ch < Wl; ch += 8) {
        for (int i2 = tid; i2 < 512; i2 += 256) {
            int rr = i2 >> 3, ww = i2 & 7;
            int gw = ch + ww;
            bool okw = (gw < Wl);
            As[rr * 9 + ww] = (okw && rbase + rr < kk) ? A[(size_t)ridx[rr] * Wl + gw] : 0u;
            Bs[rr * 9 + ww] = (okw && cbase + rr < kk) ? A[(size_t)cidx[rr] * Wl + gw] : 0u;
        }
        __syncthreads();
        if (!done) {
#pragma unroll
            for (int w = 0; w < 8; ++w) {
                unsigned a0 = As[(ty4 + 0) * 9 + w];
                unsigned a1 = As[(ty4 + 1) * 9 + w];
                unsigned a2 = As[(ty4 + 2) * 9 + w];
                unsigned a3 = As[(ty4 + 3) * 9 + w];
                unsigned b0 = Bs[(tx4 + 0) * 9 + w];
                unsigned b1 = Bs[(tx4 + 1) * 9 + w];
                unsigned b2 = Bs[(tx4 + 2) * 9 + w];
                unsigned b3 = Bs[(tx4 + 3) * 9 + w];
                acc[0][0] |= a0 & b0; acc[0][1] |= a0 & b1; acc[0][2] |= a0 & b2; acc[0][3] |= a0 & b3;
                acc[1][0] |= a1 & b0; acc[1][1] |= a1 & b1; acc[1][2] |= a1 & b2; acc[1][3] |= a1 & b3;
                acc[2][0] |= a2 & b0; acc[2][1] |= a2 & b1; acc[2][2] |= a2 & b2; acc[2][3] |= a2 & b3;
                acc[3][0] |= a3 & b0; acc[3][1] |= a3 & b1; acc[3][2] |= a3 & b2; acc[3][3] |= a3 & b3;
            }
            bool d = true;
#pragma unroll
            for (int i = 0; i < 4; ++i)
#pragma unroll
                for (int j = 0; j < 4; ++j) d = d && (acc[i][j] != 0u);
            done = d;
        }
        if (__syncthreads_and(done ? 1 : 0)) break;
    }

    int word_half = tx >> 3;
    int shift = tx4 & 31;
#pragma unroll
    for (int i = 0; i < 4; ++i) {
        int r = rbase + ty4 + i;
        if (r < kk) {
            unsigned nib = 0;
#pragma unroll
            for (int j = 0; j < 4; ++j) {
                int c = cbase + tx4 + j;
                if (c < kk && acc[i][j]) nib |= (1u << j);
            }
            if (nib) atomicOr(&obits[(ty4 + i) * 2 + word_half], nib << shift);
        }
    }
    if (!diag) {
        int wt = ty4 >> 5;
        int sht = ty4 & 31;
#pragma unroll
        for (int j = 0; j < 4; ++j) {
            int c = cbase + tx4 + j;
            if (c < kk) {
                unsigned nib = 0;
#pragma unroll
                for (int i = 0; i < 4; ++i) {
                    int r = rbase + ty4 + i;
                    if (r < kk && acc[i][j]) nib |= (1u << i);
                }
                if (nib) atomicOr(&obits_t[(tx4 + j) * 2 + wt], nib << sht);
            }
        }
    }
    __syncthreads();
    if (tid < 128) {
        int rr = tid >> 1;
        int r = rbase + rr;
        int w = blockIdx.x * 2 + (tid & 1);
        if (r < kk && w < Wout) CB[(size_t)r * Wout + w] = obits[tid];
        if (!diag) {
            int r2 = cbase + rr;
            int w2 = blockIdx.y * 2 + (tid & 1);
            if (r2 < kk && w2 < Wout) CB[(size_t)r2 * Wout + w2] = obits_t[tid];
        }
    }
}

// ---- final proj: out2 = relu(tW+b)+res ; out3 = out2 + h_in ; 512 thr ----
__global__ void k_proj_final(const float* __restrict__ t, const float* __restrict__ Wm,
                             const float* __restrict__ b, const float* __restrict__ res,
                             const float* __restrict__ hin,
                             float* __restrict__ out2, float* __restrict__ out3, int n) {
    __shared__ float Ws[64 * 64];
    __shared__ float Ts[8 * 64];
    int tid = threadIdx.x;
    int d = tid & 63;
    int r8 = tid >> 6;
    int rbase = blockIdx.x * 32;
    for (int i = tid; i < 4096; i += 512) Ws[i] = Wm[i];
    for (int pass = 0; pass < 4; ++pass) {
        int row = rbase + pass * 8 + r8;
        __syncthreads();
        Ts[tid] = (row < n) ? t[(size_t)row * DIMS + d] : 0.f;
        __syncthreads();
        if (row < n) {
            float acc = 0.f;
#pragma unroll
            for (int k = 0; k < 64; ++k)
                acc = fmaf(Ts[r8 * 64 + k], Ws[k * 64 + d], acc);
            acc = acc + b[d];
            acc = fmaxf(acc, 0.f);
            acc += res[(size_t)row * DIMS + d];
            out2[(size_t)row * DIMS + d] = acc;
            out3[(size_t)row * DIMS + d] = acc + hin[(size_t)row * DIMS + d];
        }
    }
}

extern "C" void kernel_launch(void* const* d_in, const int* in_sizes, int n_in,
                              void* d_out, int out_size) {
    (void)in_sizes; (void)n_in; (void)out_size;
    const float* g0   = (const float*)d_in[0];
    const float* h_in = (const float*)d_in[1];
    const float* dW   = (const float*)d_in[2];
    const float* db   = (const float*)d_in[3];
    const float* uW   = (const float*)d_in[4];
    const float* ub   = (const float*)d_in[5];
    const float* pW   = (const float*)d_in[6];
    const float* pb   = (const float*)d_in[7];
    const float* bW   = (const float*)d_in[8];
    const float* bb   = (const float*)d_in[9];
    float* out = (float*)d_out;
    float* out0 = out;                               // [N2,64]
    float* out1 = out + (size_t)N2 * DIMS;           // [N1,64]
    float* out2 = out1 + (size_t)N1 * DIMS;          // [N0,64]
    float* out3 = out2 + (size_t)N0 * DIMS;          // [N0,64]

    void* basep = nullptr;
    cudaGetSymbolAddress(&basep, g_arena);
    char* base = (char*)basep;
    unsigned* CB0  = (unsigned*)(base + A_CB0);
    unsigned* CB1  = (unsigned*)(base + A_CB1);
    unsigned* CB2  = (unsigned*)(base + A_CB2);
    unsigned* CB3  = (unsigned*)(base + A_CB3);
    float*    T    = (float*)(base + A_T);
    float*    U    = (float*)(base + A_U);
    float*    Hb   = (float*)(base + A_H);
    float*    D0b  = (float*)(base + A_D0);
    float*    D1b  = (float*)(base + A_D1);
    float*    D2b  = (float*)(base + A_D2);
    unsigned long long* KEYS = (unsigned long long*)(base + A_KEYS);
    int*      I0   = (int*)(base + A_I0);
    int*      I1   = (int*)(base + A_I1);
    int*      I2   = (int*)(base + A_I2);
    int*      R0   = (int*)(base + A_R0);
    int*      R1   = (int*)(base + A_R1);
    int*      R2   = (int*)(base + A_R2);
    float*    RS0  = (float*)(base + A_RS0);
    float*    RS1  = (float*)(base + A_RS1);

    // ---------------- down level 0 ----------------
    k_packspmm<<<N0, 256>>>(g0, h_in, CB0, RS0, T, N0, W0);
    k_projsc<<<(N0 + 31) / 32, 512>>>(T, dW, db, pW, pb, D0b, KEYS, N0);
    k_rank<<<((N0 + 1) / 2 + 7) / 8, 256>>>(KEYS, N0, N1, D0b, Hb, I0, R0);
    k_rowor<<<N1, 128>>>(CB0, I0, CB1, RS1);

    // ---------------- down level 1 ----------------
    k_spmm_bits<<<(N1 + 7) / 8, 256>>>(CB1, RS1, Hb, T, N1, W1);
    k_projsc<<<(N1 + 31) / 32, 512>>>(T, dW + 4096, db + 64, pW + 64, pb + 1, D1b, KEYS, N1);
    k_rank<<<((N1 + 1) / 2 + 7) / 8, 256>>>(KEYS, N1, N2, D1b, Hb, I1, R1);
    {
        dim3 grid((N2 + 63) / 64, (N2 + 63) / 64);
        k_pairb<<<grid, 256>>>(CB1, I1, N2, W1, W2, CB2);
    }

    // ---------------- down level 2 ----------------
    k_gemm_bits<<<(N2 + 15) / 16, 256>>>(CB2, Hb, T, N2, W2);
    k_projsc<<<(N2 + 31) / 32, 512>>>(T, dW + 8192, db + 128, pW + 128, pb + 2, D2b, KEYS, N2);
    k_rank<<<((N2 + 1) / 2 + 7) / 8, 256>>>(KEYS, N2, N3, D2b, Hb, I2, R2);
    {
        dim3 grid((N3 + 63) / 64, (N3 + 63) / 64);
        k_pairb<<<grid, 256>>>(CB2, I2, N3, W2, W3, CB3);
    }

    // ---------------- bottom ----------------
    k_gemm_bits<<<(N3 + 15) / 16, 256>>>(CB3, Hb, T, N3, W3);
    k_proj<<<(N3 + 31) / 32, 512>>>(T, bW, bb, nullptr, Hb, N3);

    // ---------------- up level 0: streaming unpool, gcn over CB2 ----------------
    k_unpool<<<(N2 * 32 + 255) / 256, 256>>>(Hb, R2, N3, U, N2);
    k_gemm_bits<<<(N2 + 15) / 16, 256>>>(CB2, U, T, N2, W2);
    k_proj<<<(N2 + 31) / 32, 512>>>(T, uW, ub, D2b, out0, N2);

    // ---------------- up level 1: streaming unpool, gcn over CB1 ----------------
    k_unpool<<<(N1 * 32 + 255) / 256, 256>>>(out0, R1, N2, U, N1);
    k_spmm_bits<<<(N1 + 7) / 8, 256>>>(CB1, RS1, U, T, N1, W1);
    k_proj<<<(N1 + 31) / 32, 512>>>(T, uW + 4096, ub + 64, D1b, out1, N1);

    // ---------------- up level 2: streaming unpool, gcn over CB0 ----------------
    k_unpool<<<(N0 * 32 + 255) / 256, 256>>>(out1, R0, N1, U, N0);
    k_spmm_bits<<<(N0 + 7) / 8, 256>>>(CB0, RS0, U, T, N0, W0);
    k_proj_final<<<(N0 + 31) / 32, 512>>>(T, uW + 8192, ub + 128, D0b, h_in, out2, out3, N0);
}

// round 17
// speedup vs baseline: 1.0343x; 1.0105x over previous
#include <cuda_runtime.h>
#include <cstdint>
#include <cstddef>

#define N0 4096
#define N1 3686
#define N2 2580
#define N3 1548
#define DIMS 64
#define W0 128
#define W1 116
#define W2 81
#define W3 49
#define SORTN 4096
#define FULLMASK 0xffffffffu

static __host__ __device__ constexpr size_t alignup(size_t x) { return (x + 255) & ~(size_t)255; }

static constexpr size_t A_CB0  = 0;
static constexpr size_t A_CB1  = A_CB0  + alignup((size_t)N0 * W0 * 4);
static constexpr size_t A_CB2  = A_CB1  + alignup((size_t)N1 * W1 * 4);
static constexpr size_t A_CB3  = A_CB2  + alignup((size_t)N2 * W2 * 4);
static constexpr size_t A_T    = A_CB3  + alignup((size_t)N3 * W3 * 4);
static constexpr size_t A_U    = A_T    + alignup((size_t)N0 * DIMS * 4);
static constexpr size_t A_H    = A_U    + alignup((size_t)N0 * DIMS * 4);
static constexpr size_t A_D0   = A_H    + alignup((size_t)N0 * DIMS * 4);
static constexpr size_t A_D1   = A_D0   + alignup((size_t)N0 * DIMS * 4);
static constexpr size_t A_D2   = A_D1   + alignup((size_t)N1 * DIMS * 4);
static constexpr size_t A_KEYS = A_D2   + alignup((size_t)N2 * DIMS * 4);
static constexpr size_t A_I0   = A_KEYS + alignup((size_t)SORTN * 8);
static constexpr size_t A_I1   = A_I0   + alignup((size_t)SORTN * 4);
static constexpr size_t A_I2   = A_I1   + alignup((size_t)SORTN * 4);
static constexpr size_t A_R0   = A_I2   + alignup((size_t)SORTN * 4);
static constexpr size_t A_R1   = A_R0   + alignup((size_t)SORTN * 4);
static constexpr size_t A_R2   = A_R1   + alignup((size_t)SORTN * 4);
static constexpr size_t A_RS0  = A_R2   + alignup((size_t)SORTN * 4);
static constexpr size_t A_RS1  = A_RS0  + alignup((size_t)SORTN * 4);
static constexpr size_t ARENA_BYTES = A_RS1 + alignup((size_t)SORTN * 4);

__device__ __align__(256) unsigned char g_arena[ARENA_BYTES];

// ---- XLA f32 tanh (Eigen ptanh) + logistic expansion ----
__device__ __forceinline__ float xla_tanhf(float x) {
    if (fabsf(x) < 0.0004f) return x;
    float xc = fminf(fmaxf(x, -7.90531110763549805f), 7.90531110763549805f);
    float x2 = xc * xc;
    float p = -2.76076847742355e-16f;
    p = fmaf(p, x2, 2.00018790482477e-13f);
    p = fmaf(p, x2, -8.60467152213735e-11f);
    p = fmaf(p, x2, 5.12229709037114e-08f);
    p = fmaf(p, x2, 1.48572235717979e-05f);
    p = fmaf(p, x2, 6.37261928875436e-04f);
    p = fmaf(p, x2, 4.89352455891786e-03f);
    float num = xc * p;
    float q = 1.19825839466702e-06f;
    q = fmaf(q, x2, 1.18534705686654e-04f);
    q = fmaf(q, x2, 2.26843463243900e-03f);
    q = fmaf(q, x2, 4.89352518554385e-03f);
    return num / q;
}
__device__ __forceinline__ float xla_sigmoidf(float x) {
    return fmaf(0.5f, xla_tanhf(0.5f * x), 0.5f);
}

// ---- fused: pack bits + count + t = g0 @ h (warp0 ascending, inv = 1/count) ----
__global__ void k_packspmm(const float* __restrict__ g, const float* __restrict__ h,
                           unsigned* __restrict__ bits, float* __restrict__ RS,
                           float* __restrict__ t, int n, int Wl) {
    __shared__ unsigned rb[W0];
    __shared__ int wcnt[8];
    int r = blockIdx.x;
    int tid = threadIdx.x;
    int lane = tid & 31, wp = tid >> 5;
    const float* row = g + (size_t)r * n;
    int cnt = 0;
    for (int w = wp; w < Wl; w += 8) {
        int c = (w << 5) + lane;
        float v = (c < n) ? row[c] : 0.f;
        unsigned m = __ballot_sync(FULLMASK, v != 0.f);
        if (lane == 0) { bits[(size_t)r * Wl + w] = m; rb[w] = m; cnt += __popc(m); }
    }
    if (lane == 0) wcnt[wp] = cnt;
    __syncthreads();
    if (wp == 0) {
        int s = 0;
#pragma unroll
        for (int i = 0; i < 8; ++i) s += wcnt[i];
        if (lane == 0) RS[r] = (float)s;
        float inv = 1.0f / (float)s;
        const float2* h2 = (const float2*)h;
        float a0 = 0.f, a1 = 0.f;
        for (int w = 0; w < Wl; ++w) {
            unsigned word = rb[w];
            int cb = w << 5;
            while (word) {
                int c = cb + __ffs(word) - 1;
                word &= word - 1;
                float2 v = __ldg(&h2[(size_t)c * 32 + lane]);
                a0 = fmaf(inv, v.x, a0);
                a1 = fmaf(inv, v.y, a1);
            }
        }
        ((float2*)t)[(size_t)r * 32 + lane] = make_float2(a0, a1);
    }
}

// ---- t = G @ h, bits*(1/RS); warp per row, ffs ascending; float2; 2-way MLP ----
__global__ void k_spmm_bits(const unsigned* __restrict__ CB, const float* __restrict__ RS,
                            const float* __restrict__ h, float* __restrict__ t,
                            int n, int Wl) {
    int warp = (int)((blockIdx.x * (unsigned)blockDim.x + threadIdx.x) >> 5);
    int lane = threadIdx.x & 31;
    if (warp >= n) return;
    const unsigned* row = CB + (size_t)warp * Wl;
    const float2* h2 = (const float2*)h;
    float inv = 1.0f / RS[warp];
    float a0 = 0.f, a1 = 0.f;
    for (int wb = 0; wb < Wl; wb += 32) {
        unsigned myw = (wb + lane < Wl) ? row[wb + lane] : 0u;
        unsigned any = __ballot_sync(FULLMASK, myw != 0u);
        while (any) {
            int s = __ffs(any) - 1;
            any &= any - 1;
            unsigned word = __shfl_sync(FULLMASK, myw, s);
            int cb = (wb + s) << 5;
            while (word) {
                int c1 = cb + __ffs(word) - 1;
                word &= word - 1;
                float2 v1 = __ldg(&h2[(size_t)c1 * 32 + lane]);
                if (word) {
                    int c2 = cb + __ffs(word) - 1;
                    word &= word - 1;
                    float2 v2 = __ldg(&h2[(size_t)c2 * 32 + lane]);
                    a0 = fmaf(inv, v1.x, a0); a1 = fmaf(inv, v1.y, a1);
                    a0 = fmaf(inv, v2.x, a0); a1 = fmaf(inv, v2.y, a1);
                } else {
                    a0 = fmaf(inv, v1.x, a0); a1 = fmaf(inv, v1.y, a1);
                }
            }
        }
    }
    ((float2*)t)[(size_t)warp * 32 + lane] = make_float2(a0, a1);
}

// ---- t = G @ h dense sweep (G from bits); self-popcount ----
__global__ void k_gemm_bits(const unsigned* __restrict__ CB,
                            const float* __restrict__ h, float* __restrict__ t,
                            int n, int Wl) {
    __shared__ float gs[16][65];
    __shared__ float hs[64][64];
    __shared__ float invs[16];
    int tid = threadIdx.x;
    int tx = tid & 15, ty = tid >> 4;
    int tx4 = tx * 4;
    int rbase = blockIdx.x * 16;
    {
        int lane = tid & 31, wp = tid >> 5;
        for (int rr = wp; rr < 16; rr += 8) {
            int r = rbase + rr;
            int c = 0;
            if (r < n) {
                const unsigned* rowp = CB + (size_t)r * Wl;
                for (int w = lane; w < Wl; w += 32) c += __popc(rowp[w]);
            }
#pragma unroll
            for (int off = 16; off > 0; off >>= 1) c += __shfl_xor_sync(FULLMASK, c, off);
            if (lane == 0) invs[rr] = (r < n && c > 0) ? 1.0f / (float)c : 0.f;
        }
    }
    __syncthreads();
    float acc[4] = {0.f, 0.f, 0.f, 0.f};
    const float2* h2 = (const float2*)h;

    for (int kb = 0; kb < n; kb += 64) {
        for (int i2 = tid; i2 < 1024; i2 += 256) {
            int rr = i2 >> 6, cc = i2 & 63;
            int gr = rbase + rr, gc = kb + cc;
            bool bit = (gr < n && gc < n) &&
                       ((CB[(size_t)gr * Wl + (gc >> 5)] >> (gc & 31)) & 1u);
            gs[rr][cc] = bit ? invs[rr] : 0.f;
        }
        for (int i2 = tid; i2 < 2048; i2 += 256) {
            int rr = i2 >> 5, cc = i2 & 31;
            int hr = kb + rr;
            float2 v = make_float2(0.f, 0.f);
            if (hr < n) v = __ldg(&h2[(size_t)hr * 32 + cc]);
            ((float2*)&hs[rr][0])[cc] = v;
        }
        __syncthreads();
#pragma unroll 8
        for (int kk = 0; kk < 64; ++kk) {
            float a = gs[ty][kk];
            acc[0] = fmaf(a, hs[kk][tx4 + 0], acc[0]);
            acc[1] = fmaf(a, hs[kk][tx4 + 1], acc[1]);
            acc[2] = fmaf(a, hs[kk][tx4 + 2], acc[2]);
            acc[3] = fmaf(a, hs[kk][tx4 + 3], acc[3]);
        }
        __syncthreads();
    }
    int r = rbase + ty;
    if (r < n) {
#pragma unroll
        for (int j = 0; j < 4; ++j)
            t[(size_t)r * DIMS + tx4 + j] = acc[j];
    }
}

// ---- out = relu((t @ W) + b) [+ res]; 512 thr ----
__global__ void k_proj(const float* __restrict__ t, const float* __restrict__ Wm,
                       const float* __restrict__ b, const float* __restrict__ res,
                       float* __restrict__ out, int n) {
    __shared__ float Ws[64 * 64];
    __shared__ float Ts[8 * 64];
    int tid = threadIdx.x;
    int d = tid & 63;
    int r8 = tid >> 6;
    int rbase = blockIdx.x * 32;
    for (int i = tid; i < 4096; i += 512) Ws[i] = Wm[i];
    for (int pass = 0; pass < 4; ++pass) {
        int row = rbase + pass * 8 + r8;
        __syncthreads();
        Ts[tid] = (row < n) ? t[(size_t)row * DIMS + d] : 0.f;
        __syncthreads();
        if (row < n) {
            float acc = 0.f;
#pragma unroll
            for (int k = 0; k < 64; ++k)
                acc = fmaf(Ts[r8 * 64 + k], Ws[k * 64 + d], acc);
            acc = acc + b[d];
            acc = fmaxf(acc, 0.f);
            if (res) acc += res[(size_t)row * DIMS + d];
            out[(size_t)row * DIMS + d] = acc;
        }
    }
}

// ---- fused down-proj + pool scores; 512 thr ----
__global__ void k_projsc(const float* __restrict__ t, const float* __restrict__ Wm,
                         const float* __restrict__ b, const float* __restrict__ pw,
                         const float* __restrict__ pb,
                         float* __restrict__ D, unsigned long long* __restrict__ keys,
                         int n) {
    __shared__ float Ws[64 * 64];
    __shared__ float Ts[8 * 64];
    __shared__ float Os[8 * 64];
    int tid = threadIdx.x;
    int d = tid & 63;
    int r8 = tid >> 6;
    int lane = tid & 31, w = tid >> 5;
    int rbase = blockIdx.x * 32;
    for (int i = tid; i < 4096; i += 512) Ws[i] = Wm[i];
    for (int pass = 0; pass < 4; ++pass) {
        int row = rbase + pass * 8 + r8;
        __syncthreads();
        Ts[tid] = (row < n) ? t[(size_t)row * DIMS + d] : 0.f;
        __syncthreads();
        float acc = 0.f;
#pragma unroll
        for (int k = 0; k < 64; ++k)
            acc = fmaf(Ts[r8 * 64 + k], Ws[k * 64 + d], acc);
        acc = acc + b[d];
        acc = fmaxf(acc, 0.f);
        if (row < n) D[(size_t)row * DIMS + d] = acc;
        Os[tid] = acc;
        __syncthreads();
        if ((w & 1) == 0) {
            int rr = w >> 1;
            int row2 = rbase + pass * 8 + rr;
            if (row2 < n) {
                float p = Os[rr * 64 + lane] * pw[lane];
                p = fmaf(Os[rr * 64 + lane + 32], pw[lane + 32], p);
#pragma unroll
                for (int off = 16; off > 0; off >>= 1) p += __shfl_xor_sync(FULLMASK, p, off);
                if (lane == 0) {
                    unsigned fb = __float_as_uint(xla_sigmoidf(p + pb[0]));
                    keys[row2] = ((unsigned long long)(~fb) << 32) | (unsigned)row2;
                }
            }
        }
    }
}

// ---- exact top-k by ranking, 2 items per warp + fused gated gather ----
__global__ void k_rank(const unsigned long long* __restrict__ keys, int n, int k,
                       const float* __restrict__ D, float* __restrict__ Hb,
                       int* __restrict__ idx_out, int* __restrict__ RANK) {
    int wid = (int)((blockIdx.x * (unsigned)blockDim.x + threadIdx.x) >> 5);
    int lane = threadIdx.x & 31;
    int i0 = wid * 2, i1 = i0 + 1;
    if (i0 >= n) return;
    unsigned long long k0 = keys[i0];
    unsigned long long k1 = (i1 < n) ? keys[i1] : 0xFFFFFFFFFFFFFFFFull;
    int c0 = 0, c1 = 0;
    int j = lane;
    for (; j + 32 < n; j += 64) {
        unsigned long long a = keys[j], bk = keys[j + 32];
        c0 += (a < k0) ? 1 : 0; c0 += (bk < k0) ? 1 : 0;
        c1 += (a < k1) ? 1 : 0; c1 += (bk < k1) ? 1 : 0;
    }
    for (; j < n; j += 32) {
        unsigned long long a = keys[j];
        c0 += (a < k0) ? 1 : 0;
        c1 += (a < k1) ? 1 : 0;
    }
#pragma unroll
    for (int off = 16; off > 0; off >>= 1) {
        c0 += __shfl_xor_sync(FULLMASK, c0, off);
        c1 += __shfl_xor_sync(FULLMASK, c1, off);
    }
    if (lane == 0) RANK[i0] = c0;
    if (c0 < k) {
        if (lane == 0) idx_out[c0] = i0;
        float s = __uint_as_float(~(unsigned)(k0 >> 32));
        float2 v = ((const float2*)D)[(size_t)i0 * 32 + lane];
        ((float2*)Hb)[(size_t)c0 * 32 + lane] = make_float2(v.x * s, v.y * s);
    }
    if (i1 < n) {
        if (lane == 0) RANK[i1] = c1;
        if (c1 < k) {
            if (lane == 0) idx_out[c1] = i1;
            float s = __uint_as_float(~(unsigned)(k1 >> 32));
            float2 v = ((const float2*)D)[(size_t)i1 * 32 + lane];
            ((float2*)Hb)[(size_t)c1 * 32 + lane] = make_float2(v.x * s, v.y * s);
        }
    }
}

// ---- streaming unpool: u[r] = RANK[r] < k ? src[RANK[r]] : 0 ; float2 ----
__global__ void k_unpool(const float* __restrict__ src, const int* __restrict__ RANK,
                         int kvalid, float* __restrict__ u, int n) {
    int i = blockIdx.x * 256 + threadIdx.x;
    if (i >= n * 32) return;
    int r = i >> 5, d = i & 31;
    int rk = RANK[r];
    float2 v = make_float2(0.f, 0.f);
    if (rk < kvalid) v = ((const float2*)src)[(size_t)rk * 32 + d];
    ((float2*)u)[(size_t)r * 32 + d] = v;
}

// ---- level-0 2-hop row-OR: 256 thr, split OR halves + 8-warp gather ----
__global__ void k_rowor(const unsigned* __restrict__ BITS0, const int* __restrict__ idx,
                        unsigned* __restrict__ CB1o, float* __restrict__ RS1o) {
    __shared__ unsigned accs[W0];
    __shared__ unsigned accs2[W0];
    __shared__ int nb[512];
    __shared__ int nbcnt;
    __shared__ int idxs[N1];
    __shared__ int cnt_sh;
    int i = blockIdx.x;
    int t = threadIdx.x;            // 256 threads
    if (t == 0) { nbcnt = 0; cnt_sh = 0; }
    __syncthreads();
    if (t < W0) {
        unsigned w = BITS0[(size_t)idx[i] * W0 + t];
        if (w) {
            int c = __popc(w);
            int basei = atomicAdd(&nbcnt, c);
            int cb = t << 5;
            while (w) {
                nb[basei++] = cb + __ffs(w) - 1;
                w &= w - 1;
            }
        }
    }
    for (int j = t; j < N1; j += 256) idxs[j] = idx[j];
    __syncthreads();
    int cnt = nbcnt;
    int tw = t & 127;
    int half = t >> 7;
    unsigned a = 0;
    for (int q = half; q < cnt; q += 2)
        a |= BITS0[(size_t)nb[q] * W0 + tw];
    if (half == 0) accs[tw] = a; else accs2[tw] = a;
    __syncthreads();
    if (t < W0) accs[t] |= accs2[t];
    __syncthreads();
    int lane = t & 31, wp = t >> 5;  // 8 warps
    int lc = 0;
    for (int ow = wp; ow < W1; ow += 8) {
        int j = (ow << 5) + lane;
        unsigned bit = 0;
        if (j < N1) {
            int col = idxs[j];
            bit = (accs[col >> 5] >> (col & 31)) & 1u;
        }
        unsigned m = __ballot_sync(FULLMASK, bit);
        if (lane == 0) {
            CB1o[(size_t)i * W1 + ow] = m;
            lc += __popc(m);
        }
    }
    if (lane == 0 && lc) atomicAdd(&cnt_sh, lc);
    __syncthreads();
    if (t == 0) RS1o[i] = (float)cnt_sh;
}

// ---- pairwise 2-hop, SYMMETRIC: only bx>=by blocks; emit tile + mirror ----
__global__ void k_pairb(const unsigned* __restrict__ A, const int* __restrict__ idx,
                        int kk, int Wl, int Wout, unsigned* __restrict__ CB) {
    if (blockIdx.x < blockIdx.y) return;
    __shared__ unsigned As[64 * 9];
    __shared__ unsigned Bs[64 * 9];
    __shared__ unsigned obits[128];
    __shared__ unsigned obits_t[128];
    __shared__ int ridx[64], cidx[64];
    int tid = threadIdx.x;
    int tx = tid & 15, ty = tid >> 4;
    int rbase = blockIdx.y * 64, cbase = blockIdx.x * 64;
    bool diag = (blockIdx.x == blockIdx.y);
    int ty4 = ty * 4, tx4 = tx * 4;
    if (tid < 128) { obits[tid] = 0u; obits_t[tid] = 0u; }
    if (tid < 64) {
        int r = rbase + tid;
        ridx[tid] = (r < kk) ? idx[r] : 0;
        int c = cbase + tid;
        cidx[tid] = (c < kk) ? idx[c] : 0;
    }

    unsigned acc[4][4];
#pragma unroll
    for (int i = 0; i < 4; ++i)
#pragma unroll
        for (int j = 0; j < 4; ++j) {
            bool valid = (rbase + ty4 + i < kk) && (cbase + tx4 + j < kk);
            acc[i][j] = valid ? 0u : 1u;
        }
    __syncthreads();

    bool done = false;
    for (int ch = 0; ch < Wl; ch += 8) {
        for (int i2 = tid; i2 < 512; i2 += 256) {
            int rr = i2 >> 3, ww = i2 & 7;
            int gw = ch + ww;
            bool okw = (gw < Wl);
            As[rr * 9 + ww] = (okw && rbase + rr < kk) ? A[(size_t)ridx[rr] * Wl + gw] : 0u;
            Bs[rr * 9 + ww] = (okw && cbase + rr < kk) ? A[(size_t)cidx[rr] * Wl + gw] : 0u;
        }
        __syncthreads();
        if (!done) {
#pragma unroll
            for (int w = 0; w < 8; ++w) {
                unsigned a0 = As[(ty4 + 0) * 9 + w];
                unsigned a1 = As[(ty4 + 1) * 9 + w];
                unsigned a2 = As[(ty4 + 2) * 9 + w];
                unsigned a3 = As[(ty4 + 3) * 9 + w];
                unsigned b0 = Bs[(tx4 + 0) * 9 + w];
                unsigned b1 = Bs[(tx4 + 1) * 9 + w];
                unsigned b2 = Bs[(tx4 + 2) * 9 + w];
                unsigned b3 = Bs[(tx4 + 3) * 9 + w];
                acc[0][0] |= a0 & b0; acc[0][1] |= a0 & b1; acc[0][2] |= a0 & b2; acc[0][3] |= a0 & b3;
                acc[1][0] |= a1 & b0; acc[1][1] |= a1 & b1; acc[1][2] |= a1 & b2; acc[1][3] |= a1 & b3;
                acc[2][0] |= a2 & b0; acc[2][1] |= a2 & b1; acc[2][2] |= a2 & b2; acc[2][3] |= a2 & b3;
                acc[3][0] |= a3 & b0; acc[3][1] |= a3 & b1; acc[3][2] |= a3 & b2; acc[3][3] |= a3 & b3;
            }
            bool d = true;
#pragma unroll
            for (int i = 0; i < 4; ++i)
#pragma unroll
                for (int j = 0; j < 4; ++j) d = d && (acc[i][j] != 0u);
            done = d;
        }
        if (__syncthreads_and(done ? 1 : 0)) break;
    }

    int word_half = tx >> 3;
    int shift = tx4 & 31;
#pragma unroll
    for (int i = 0; i < 4; ++i) {
        int r = rbase + ty4 + i;
        if (r < kk) {
            unsigned nib = 0;
#pragma unroll
            for (int j = 0; j < 4; ++j) {
                int c = cbase + tx4 + j;
                if (c < kk && acc[i][j]) nib |= (1u << j);
            }
            if (nib) atomicOr(&obits[(ty4 + i) * 2 + word_half], nib << shift);
        }
    }
    if (!diag) {
        int wt = ty4 >> 5;
        int sht = ty4 & 31;
#pragma unroll
        for (int j = 0; j < 4; ++j) {
            int c = cbase + tx4 + j;
            if (c < kk) {
                unsigned nib = 0;
#pragma unroll
                for (int i = 0; i < 4; ++i) {
                    int r = rbase + ty4 + i;
                    if (r < kk && acc[i][j]) nib |= (1u << i);
                }
                if (nib) atomicOr(&obits_t[(tx4 + j) * 2 + wt], nib << sht);
            }
        }
    }
    __syncthreads();
    if (tid < 128) {
        int rr = tid >> 1;
        int r = rbase + rr;
        int w = blockIdx.x * 2 + (tid & 1);
        if (r < kk && w < Wout) CB[(size_t)r * Wout + w] = obits[tid];
        if (!diag) {
            int r2 = cbase + rr;
            int w2 = blockIdx.y * 2 + (tid & 1);
            if (r2 < kk && w2 < Wout) CB[(size_t)r2 * Wout + w2] = obits_t[tid];
        }
    }
}

// ---- final proj: out2 = relu(tW+b)+res ; out3 = out2 + h_in ; 512 thr ----
__global__ void k_proj_final(const float* __restrict__ t, const float* __restrict__ Wm,
                             const float* __restrict__ b, const float* __restrict__ res,
                             const float* __restrict__ hin,
                             float* __restrict__ out2, float* __restrict__ out3, int n) {
    __shared__ float Ws[64 * 64];
    __shared__ float Ts[8 * 64];
    int tid = threadIdx.x;
    int d = tid & 63;
    int r8 = tid >> 6;
    int rbase = blockIdx.x * 32;
    for (int i = tid; i < 4096; i += 512) Ws[i] = Wm[i];
    for (int pass = 0; pass < 4; ++pass) {
        int row = rbase + pass * 8 + r8;
        __syncthreads();
        Ts[tid] = (row < n) ? t[(size_t)row * DIMS + d] : 0.f;
        __syncthreads();
        if (row < n) {
            float acc = 0.f;
#pragma unroll
            for (int k = 0; k < 64; ++k)
                acc = fmaf(Ts[r8 * 64 + k], Ws[k * 64 + d], acc);
            acc = acc + b[d];
            acc = fmaxf(acc, 0.f);
            acc += res[(size_t)row * DIMS + d];
            out2[(size_t)row * DIMS + d] = acc;
            out3[(size_t)row * DIMS + d] = acc + hin[(size_t)row * DIMS + d];
        }
    }
}

extern "C" void kernel_launch(void* const* d_in, const int* in_sizes, int n_in,
                              void* d_out, int out_size) {
    (void)in_sizes; (void)n_in; (void)out_size;
    const float* g0   = (const float*)d_in[0];
    const float* h_in = (const float*)d_in[1];
    const float* dW   = (const float*)d_in[2];
    const float* db   = (const float*)d_in[3];
    const float* uW   = (const float*)d_in[4];
    const float* ub   = (const float*)d_in[5];
    const float* pW   = (const float*)d_in[6];
    const float* pb   = (const float*)d_in[7];
    const float* bW   = (const float*)d_in[8];
    const float* bb   = (const float*)d_in[9];
    float* out = (float*)d_out;
    float* out0 = out;                               // [N2,64]
    float* out1 = out + (size_t)N2 * DIMS;           // [N1,64]
    float* out2 = out1 + (size_t)N1 * DIMS;          // [N0,64]
    float* out3 = out2 + (size_t)N0 * DIMS;          // [N0,64]

    void* basep = nullptr;
    cudaGetSymbolAddress(&basep, g_arena);
    char* base = (char*)basep;
    unsigned* CB0  = (unsigned*)(base + A_CB0);
    unsigned* CB1  = (unsigned*)(base + A_CB1);
    unsigned* CB2  = (unsigned*)(base + A_CB2);
    unsigned* CB3  = (unsigned*)(base + A_CB3);
    float*    T    = (float*)(base + A_T);
    float*    U    = (float*)(base + A_U);
    float*    Hb   = (float*)(base + A_H);
    float*    D0b  = (float*)(base + A_D0);
    float*    D1b  = (float*)(base + A_D1);
    float*    D2b  = (float*)(base + A_D2);
    unsigned long long* KEYS = (unsigned long long*)(base + A_KEYS);
    int*      I0   = (int*)(base + A_I0);
    int*      I1   = (int*)(base + A_I1);
    int*      I2   = (int*)(base + A_I2);
    int*      R0   = (int*)(base + A_R0);
    int*      R1   = (int*)(base + A_R1);
    int*      R2   = (int*)(base + A_R2);
    float*    RS0  = (float*)(base + A_RS0);
    float*    RS1  = (float*)(base + A_RS1);

    // ---------------- down level 0 ----------------
    k_packspmm<<<N0, 256>>>(g0, h_in, CB0, RS0, T, N0, W0);
    k_projsc<<<(N0 + 31) / 32, 512>>>(T, dW, db, pW, pb, D0b, KEYS, N0);
    k_rank<<<((N0 + 1) / 2 + 7) / 8, 256>>>(KEYS, N0, N1, D0b, Hb, I0, R0);
    k_rowor<<<N1, 256>>>(CB0, I0, CB1, RS1);

    // ---------------- down level 1 ----------------
    k_spmm_bits<<<(N1 + 7) / 8, 256>>>(CB1, RS1, Hb, T, N1, W1);
    k_projsc<<<(N1 + 31) / 32, 512>>>(T, dW + 4096, db + 64, pW + 64, pb + 1, D1b, KEYS, N1);
    k_rank<<<((N1 + 1) / 2 + 7) / 8, 256>>>(KEYS, N1, N2, D1b, Hb, I1, R1);
    {
        dim3 grid((N2 + 63) / 64, (N2 + 63) / 64);
        k_pairb<<<grid, 256>>>(CB1, I1, N2, W1, W2, CB2);
    }

    // ---------------- down level 2 ----------------
    k_gemm_bits<<<(N2 + 15) / 16, 256>>>(CB2, Hb, T, N2, W2);
    k_projsc<<<(N2 + 31) / 32, 512>>>(T, dW + 8192, db + 128, pW + 128, pb + 2, D2b, KEYS, N2);
    k_rank<<<((N2 + 1) / 2 + 7) / 8, 256>>>(KEYS, N2, N3, D2b, Hb, I2, R2);
    {
        dim3 grid((N3 + 63) / 64, (N3 + 63) / 64);
        k_pairb<<<grid, 256>>>(CB2, I2, N3, W2, W3, CB3);
    }

    // ---------------- bottom ----------------
    k_gemm_bits<<<(N3 + 15) / 16, 256>>>(CB3, Hb, T, N3, W3);
    k_proj<<<(N3 + 31) / 32, 512>>>(T, bW, bb, nullptr, Hb, N3);

    // ---------------- up level 0: streaming unpool, gcn over CB2 ----------------
    k_unpool<<<(N2 * 32 + 255) / 256, 256>>>(Hb, R2, N3, U, N2);
    k_gemm_bits<<<(N2 + 15) / 16, 256>>>(CB2, U, T, N2, W2);
    k_proj<<<(N2 + 31) / 32, 512>>>(T, uW, ub, D2b, out0, N2);

    // ---------------- up level 1: streaming unpool, gcn over CB1 ----------------
    k_unpool<<<(N1 * 32 + 255) / 256, 256>>>(out0, R1, N2, U, N1);
    k_spmm_bits<<<(N1 + 7) / 8, 256>>>(CB1, RS1, U, T, N1, W1);
    k_proj<<<(N1 + 31) / 32, 512>>>(T, uW + 4096, ub + 64, D1b, out1, N1);

    // ---------------- up level 2: streaming unpool, gcn over CB0 ----------------
    k_unpool<<<(N0 * 32 + 255) / 256, 256>>>(out1, R0, N1, U, N0);
    k_spmm_bits<<<(N0 + 7) / 8, 256>>>(CB0, RS0, U, T, N0, W0);
    k_proj_final<<<(N0 + 31) / 32, 512>>>(T, uW + 8192, ub + 128, D0b, h_in, out2, out3, N0);
}